// round 14
// baseline (speedup 1.0000x reference)
#include <cuda_runtime.h>
#include <cuda_bf16.h>
#include <math.h>
#include <stdint.h>

// ---------------------------------------------------------------------------
// Problem constants
// ---------------------------------------------------------------------------
#define CHAR_SIZE 128
#define CE        64
#define HE        128      // char LSTM hidden
#define WE        256
#define HP        256      // word LSTM hidden
#define TAGS      50
#define NWORDS    8192
#define MAXCH     16
#define G_E       (4*HE)   // 512
#define G_P       (4*HP)   // 1024
#define KIN_P     (WE+HE)  // 384
#define WCLUSTER  16       // word-LSTM cluster size (non-portable)

// ---------------------------------------------------------------------------
// Scratch (static device globals; no allocation allowed)
// ---------------------------------------------------------------------------
__device__ float g_tablep[CHAR_SIZE * G_E];      // [ch][u*4+q] char xgate table (+biases)
__device__ float g_WTe[HE * G_E];                // [k][u*4+q]  permuted Whh_e
__device__ float g_WpT[KIN_P * G_P];             // [k][g]      transposed Wih_p
__device__ float g_xg[(size_t)NWORDS * G_P];     // word-LSTM input gates (+biases)
__device__ float g_hchar[NWORDS * HE];           // char LSTM final hidden
__device__ float g_hs[NWORDS * HP];              // word LSTM hidden states

// ---------------------------------------------------------------------------
// Packed f32x2 helpers (Blackwell: fma.rn.f32x2 only reachable via PTX)
// ---------------------------------------------------------------------------
#define FMA_F32X2(acc, a, b) \
    asm("fma.rn.f32x2 %0, %1, %2, %0;" : "+l"(acc) : "l"(a), "l"(b))
#define SPLAT_F32X2(out, f) \
    asm("mov.b64 %0, {%1, %1};" : "=l"(out) : "f"(f))
#define UNPACK_F32X2(lo, hi, v) \
    asm("mov.b64 {%0, %1}, %2;" : "=f"(lo), "=f"(hi) : "l"(v))

// ---------------------------------------------------------------------------
// Fast activations (exact-ish path, used in char/tag kernels)
// ---------------------------------------------------------------------------
__device__ __forceinline__ float sigf(float x) {
    return __fdividef(1.0f, 1.0f + __expf(-x));
}
__device__ __forceinline__ float tanhfast(float x) {
    x = fminf(9.0f, fmaxf(-9.0f, x));
    float e = __expf(-2.0f * x);
    return __fdividef(1.0f - e, 1.0f + e);
}
// MUFU tanh path (word-LSTM tail only; single-instruction activations)
__device__ __forceinline__ float tanh_mufu(float x) {
    float r;
    asm("tanh.approx.f32 %0, %1;" : "=f"(r) : "f"(x));
    return r;
}
__device__ __forceinline__ float sig_mufu(float x) {
    float r;
    asm("tanh.approx.f32 %0, %1;" : "=f"(r) : "f"(0.5f * x));
    return fmaf(0.5f, r, 0.5f);
}

// ---------------------------------------------------------------------------
// Prep kernels
// ---------------------------------------------------------------------------
__global__ void prep_table_kernel(const float* __restrict__ char_emb,
                                  const float* __restrict__ Wih_e,
                                  const float* __restrict__ bih_e,
                                  const float* __restrict__ bhh_e) {
    int idx = blockIdx.x * 256 + threadIdx.x;        // 0 .. 128*512-1
    int ch = idx >> 9;
    int col = idx & 511;
    int u = col >> 2, q = col & 3;
    int row = q * HE + u;
    float acc = bih_e[row] + bhh_e[row];
    const float* ce = char_emb + ch * CE;
    const float* wr = Wih_e + row * CE;
#pragma unroll 16
    for (int k = 0; k < CE; k++) acc = fmaf(ce[k], wr[k], acc);
    g_tablep[idx] = acc;
}

__global__ void prep_wte_kernel(const float* __restrict__ Whh_e) {
    int idx = blockIdx.x * 256 + threadIdx.x;
    int k = idx >> 9;
    int col = idx & 511;
    int u = col >> 2, q = col & 3;
    g_WTe[idx] = Whh_e[(q * HE + u) * HE + k];
}

__global__ void prep_wpt_kernel(const float* __restrict__ Wih_p) {
    int idx = blockIdx.x * 256 + threadIdx.x;
    int k = idx >> 10;
    int g = idx & 1023;
    g_WpT[idx] = Wih_p[g * KIN_P + k];
}

// ---------------------------------------------------------------------------
// Char LSTM: 128 blocks x 512 threads, 64 words per block.
// NEW retile: thread = 8 words x 1 unit (all 4 gates); 2 phases of 64 units.
// 3 LDS per 32 MAC (was 2 per 16); wt staged [128][256] = 128 KB.
// smem: hA[128][64], hB[128][64], wt[128][256], lens, chs  (~193 KB)
// ---------------------------------------------------------------------------
#define CHAR_SMEM_BYTES ((8192 + 8192 + 32768 + 128) * 4)

__global__ void __launch_bounds__(512, 1)
char_lstm_kernel(const int* __restrict__ char_ids,
                 const int* __restrict__ char_lengths) {
    extern __shared__ __align__(16) float sm[];
    float* hA = sm;                         // [128][64]
    float* hB = sm + 8192;                  // [128][64]
    float* wt = sm + 16384;                 // [128][256]
    int*   lens = (int*)(sm + 49152);       // [64]
    int*   chs  = (int*)(sm + 49152 + 64);  // [64]

    int tid = threadIdx.x;
    int wbase = blockIdx.x * 64;
    int w0 = (tid & 7) * 8;      // words w0..w0+7
    int uu = tid >> 3;           // 0..63 (unit within phase)

    for (int i = tid; i < 8192; i += 512) hA[i] = 0.0f;
    if (tid < 64) lens[tid] = char_lengths[wbase + tid];
    __syncthreads();

    int len8[8];
#pragma unroll
    for (int j = 0; j < 8; j++) len8[j] = lens[w0 + j];

    float c_reg[16];             // cells: 2 phases x 8 words
#pragma unroll
    for (int i = 0; i < 16; i++) c_reg[i] = 0.0f;

    for (int t = 0; t < MAXCH; t++) {
        if (tid < 64) chs[tid] = char_ids[(wbase + tid) * MAXCH + t];
        __syncthreads();
        float* hc = (t & 1) ? hB : hA;
        float* hn = (t & 1) ? hA : hB;

        for (int ph = 0; ph < 2; ph++) {
            int u = ph * 64 + uu;                // unit 0..127

            // stage wt[k][0..255] = WTe[k][ph*256 .. +255]
#pragma unroll
            for (int j = 0; j < 16; j++) {
                int lin = tid + 512 * j;          // 0..8191 float4 slots
                int k = lin >> 6;
                int c4 = lin & 63;
                *(float4*)(wt + k * 256 + c4 * 4) =
                    *(const float4*)(g_WTe + k * G_E + ph * 256 + c4 * 4);
            }
            __syncthreads();

            // acc2[wp][g]: word-pair wp 0..3, gate g 0..3
            unsigned long long acc2[4][4];
#pragma unroll
            for (int a = 0; a < 4; a++)
#pragma unroll
                for (int b = 0; b < 4; b++) acc2[a][b] = 0ull;

#pragma unroll 4
            for (int k = 0; k < HE; k++) {
                float4 b = *(const float4*)(wt + k * 256 + uu * 4);
                ulonglong2 avA = *(const ulonglong2*)(hc + k * 64 + w0);
                ulonglong2 avB = *(const ulonglong2*)(hc + k * 64 + w0 + 4);
                unsigned long long bx, by, bz, bw;
                SPLAT_F32X2(bx, b.x);
                SPLAT_F32X2(by, b.y);
                SPLAT_F32X2(bz, b.z);
                SPLAT_F32X2(bw, b.w);
                FMA_F32X2(acc2[0][0], avA.x, bx);
                FMA_F32X2(acc2[0][1], avA.x, by);
                FMA_F32X2(acc2[0][2], avA.x, bz);
                FMA_F32X2(acc2[0][3], avA.x, bw);
                FMA_F32X2(acc2[1][0], avA.y, bx);
                FMA_F32X2(acc2[1][1], avA.y, by);
                FMA_F32X2(acc2[1][2], avA.y, bz);
                FMA_F32X2(acc2[1][3], avA.y, bw);
                FMA_F32X2(acc2[2][0], avB.x, bx);
                FMA_F32X2(acc2[2][1], avB.x, by);
                FMA_F32X2(acc2[2][2], avB.x, bz);
                FMA_F32X2(acc2[2][3], avB.x, bw);
                FMA_F32X2(acc2[3][0], avB.y, bx);
                FMA_F32X2(acc2[3][1], avB.y, by);
                FMA_F32X2(acc2[3][2], avB.y, bz);
                FMA_F32X2(acc2[3][3], avB.y, bw);
            }

            float accf[8][4];
#pragma unroll
            for (int wp = 0; wp < 4; wp++)
#pragma unroll
                for (int g = 0; g < 4; g++)
                    UNPACK_F32X2(accf[2 * wp][g], accf[2 * wp + 1][g], acc2[wp][g]);

            float4 holdA = *(const float4*)(hc + u * 64 + w0);
            float4 holdB = *(const float4*)(hc + u * 64 + w0 + 4);
            float hv[8] = {holdA.x, holdA.y, holdA.z, holdA.w,
                           holdB.x, holdB.y, holdB.z, holdB.w};
            float hnv[8];
#pragma unroll
            for (int j = 0; j < 8; j++) {
                float4 tb = *(const float4*)(g_tablep + chs[w0 + j] * G_E + u * 4);
                float pi = accf[j][0] + tb.x;
                float pf = accf[j][1] + tb.y;
                float pg = accf[j][2] + tb.z;
                float po = accf[j][3] + tb.w;
                float iv = sigf(pi), fv = sigf(pf);
                float gv = tanhfast(pg), ov = sigf(po);
                float cold = c_reg[ph * 8 + j];
                float cn = fmaf(fv, cold, iv * gv);
                float hh = ov * tanhfast(cn);
                bool msk = (t < len8[j]);
                c_reg[ph * 8 + j] = msk ? cn : cold;
                hnv[j] = msk ? hh : hv[j];
            }
            float4 oA, oB;
            oA.x = hnv[0]; oA.y = hnv[1]; oA.z = hnv[2]; oA.w = hnv[3];
            oB.x = hnv[4]; oB.y = hnv[5]; oB.z = hnv[6]; oB.w = hnv[7];
            *(float4*)(hn + u * 64 + w0) = oA;
            *(float4*)(hn + u * 64 + w0 + 4) = oB;
            __syncthreads();
        }
    }

    // final h in hA (t=15 wrote hA)
#pragma unroll
    for (int ph = 0; ph < 2; ph++) {
        int u = ph * 64 + uu;
        float4 hvA = *(const float4*)(hA + u * 64 + w0);
        float4 hvB = *(const float4*)(hA + u * 64 + w0 + 4);
        g_hchar[(wbase + w0 + 0) * HE + u] = hvA.x;
        g_hchar[(wbase + w0 + 1) * HE + u] = hvA.y;
        g_hchar[(wbase + w0 + 2) * HE + u] = hvA.z;
        g_hchar[(wbase + w0 + 3) * HE + u] = hvA.w;
        g_hchar[(wbase + w0 + 4) * HE + u] = hvB.x;
        g_hchar[(wbase + w0 + 5) * HE + u] = hvB.y;
        g_hchar[(wbase + w0 + 6) * HE + u] = hvB.z;
        g_hchar[(wbase + w0 + 7) * HE + u] = hvB.w;
    }
}

// ---------------------------------------------------------------------------
// Word-LSTM input gates: xg[n][g] = feats[n] @ Wih_p.T + bih_p + bhh_p
// ---------------------------------------------------------------------------
__global__ void __launch_bounds__(256)
xgates_kernel(const float* __restrict__ word_emb,
              const int* __restrict__ sentence,
              const float* __restrict__ bih_p,
              const float* __restrict__ bhh_p) {
    __shared__ float As[64 * 65];
    __shared__ float Bs[64 * 64];
    __shared__ int   sent[64];

    int bg = blockIdx.x;   // 0..15
    int bn = blockIdx.y;   // 0..127
    int tid = threadIdx.x;
    if (tid < 64) sent[tid] = sentence[bn * 64 + tid];

    int n0 = (tid >> 4) << 2;
    int g0 = (tid & 15) << 2;

    float acc[4][4];
#pragma unroll
    for (int a = 0; a < 4; a++)
#pragma unroll
        for (int b = 0; b < 4; b++) acc[a][b] = 0.0f;

    for (int kc = 0; kc < 6; kc++) {
        __syncthreads();
#pragma unroll
        for (int j = 0; j < 16; j++) {
            int lin = tid + 256 * j;                 // 0..4095
            int nn = lin >> 6;
            int k = lin & 63;
            int kk = kc * 64 + k;
            float v;
            if (kk < WE) v = word_emb[(size_t)sent[nn] * WE + kk];
            else         v = g_hchar[(bn * 64 + nn) * HE + (kk - WE)];
            As[nn * 65 + k] = v;
            Bs[nn * 64 + k] = g_WpT[(size_t)(kc * 64 + nn) * G_P + bg * 64 + k];
        }
        __syncthreads();
#pragma unroll 4
        for (int k = 0; k < 64; k++) {
            float4 b = *(const float4*)(Bs + k * 64 + g0);
            float a0 = As[(n0 + 0) * 65 + k];
            float a1 = As[(n0 + 1) * 65 + k];
            float a2 = As[(n0 + 2) * 65 + k];
            float a3 = As[(n0 + 3) * 65 + k];
            acc[0][0] = fmaf(a0, b.x, acc[0][0]);
            acc[0][1] = fmaf(a0, b.y, acc[0][1]);
            acc[0][2] = fmaf(a0, b.z, acc[0][2]);
            acc[0][3] = fmaf(a0, b.w, acc[0][3]);
            acc[1][0] = fmaf(a1, b.x, acc[1][0]);
            acc[1][1] = fmaf(a1, b.y, acc[1][1]);
            acc[1][2] = fmaf(a1, b.z, acc[1][2]);
            acc[1][3] = fmaf(a1, b.w, acc[1][3]);
            acc[2][0] = fmaf(a2, b.x, acc[2][0]);
            acc[2][1] = fmaf(a2, b.y, acc[2][1]);
            acc[2][2] = fmaf(a2, b.z, acc[2][2]);
            acc[2][3] = fmaf(a2, b.w, acc[2][3]);
            acc[3][0] = fmaf(a3, b.x, acc[3][0]);
            acc[3][1] = fmaf(a3, b.y, acc[3][1]);
            acc[3][2] = fmaf(a3, b.z, acc[3][2]);
            acc[3][3] = fmaf(a3, b.w, acc[3][3]);
        }
    }

    int ggl = bg * 64 + g0;
    float4 bi = *(const float4*)(bih_p + ggl);
    float4 bh = *(const float4*)(bhh_p + ggl);
#pragma unroll
    for (int l = 0; l < 4; l++) {
        float4 o;
        o.x = acc[l][0] + bi.x + bh.x;
        o.y = acc[l][1] + bi.y + bh.y;
        o.z = acc[l][2] + bi.z + bh.z;
        o.w = acc[l][3] + bi.w + bh.w;
        *(float4*)(g_xg + (size_t)(bn * 64 + n0 + l) * G_P + ggl) = o;
    }
}

// ---------------------------------------------------------------------------
// Word LSTM: 16-CTA non-portable cluster, packed f32x2 matvec,
// st.async.b64 broadcast, 4 per-k-slice mbarriers, MUFU activations.
// Micro-opts this round: acquire.cta wait scope; 4-accumulator matvec.
// ---------------------------------------------------------------------------
__device__ __forceinline__ uint32_t cluster_rank_() {
    uint32_t r;
    asm("mov.u32 %0, %%cluster_ctarank;" : "=r"(r));
    return r;
}
__device__ __forceinline__ void cluster_sync_() {
    asm volatile("barrier.cluster.arrive.aligned;" ::: "memory");
    asm volatile("barrier.cluster.wait.aligned;" ::: "memory");
}
__device__ __forceinline__ uint32_t mapa_u32(uint32_t la, int r) {
    uint32_t ra;
    asm("mapa.shared::cluster.u32 %0, %1, %2;" : "=r"(ra) : "r"(la), "r"(r));
    return ra;
}
__device__ __forceinline__ void mbar_init_(uint32_t bar, uint32_t cnt) {
    asm volatile("mbarrier.init.shared.b64 [%0], %1;" :: "r"(bar), "r"(cnt) : "memory");
}
__device__ __forceinline__ void mbar_arrive_expect_(uint32_t bar, uint32_t bytes) {
    asm volatile("mbarrier.arrive.expect_tx.shared.b64 _, [%0], %1;"
                 :: "r"(bar), "r"(bytes) : "memory");
}
__device__ __forceinline__ void mbar_wait_parity_(uint32_t bar, uint32_t ph) {
    asm volatile(
        "{\n\t"
        ".reg .pred P1;\n\t"
        "WL_%=:\n\t"
        "mbarrier.try_wait.parity.acquire.cta.shared::cta.b64 P1, [%0], %1, 0x989680;\n\t"
        "@P1 bra.uni WD_%=;\n\t"
        "bra.uni WL_%=;\n\t"
        "WD_%=:\n\t"
        "}"
        :: "r"(bar), "r"(ph) : "memory");
}
__device__ __forceinline__ void st_async_b64_(uint32_t raddr, unsigned long long v,
                                              uint32_t rbar) {
    asm volatile(
        "st.async.shared::cluster.mbarrier::complete_tx::bytes.b64 [%0], %1, [%2];"
        :: "r"(raddr), "l"(v), "r"(rbar) : "memory");
}

__global__ void __launch_bounds__(512, 1) __cluster_dims__(WCLUSTER, 1, 1)
word_lstm_kernel(const float* __restrict__ Whh_p) {
    __shared__ __align__(16) float hbuf[2][HP];      // h double-buffer
    // pacc4[p][sq*64 + q*16 + u] component = s&3  (s = k-slice-of-32, 0..7)
    __shared__ __align__(16) float4 pacc4[2][128];
    __shared__ __align__(8) unsigned long long hbar[8];  // [parity*4 + slice64]

    int rank = (int)cluster_rank_();
    int tid = threadIdx.x;
    int w = tid >> 5, lane = tid & 31;
    int q = w & 3;                        // gate quadrant
    int ks2 = w >> 2;                     // 64-wide k-slice 0..3
    int u = lane & 15;                    // unit within CTA
    int khalf = lane >> 4;                // 32-wide half within slice
    int s = ks2 * 2 + khalf;              // 32-wide k-slice 0..7
    int grow = q * HP + rank * 16 + u;    // global gate row 0..1023
    int k0 = ks2 * 64 + khalf * 32;       // this thread's k range [k0, k0+32)

    // resident packed weights: Whh_p[grow][k0 .. k0+32) as 16 f32x2
    unsigned long long wreg[16];
    {
        const float* wp = Whh_p + (size_t)grow * HP + k0;
#pragma unroll
        for (int i = 0; i < 8; i++) {
            ulonglong2 v = *(const ulonglong2*)(wp + i * 4);
            wreg[2 * i] = v.x;
            wreg[2 * i + 1] = v.y;
        }
    }

    ((float*)hbuf)[tid] = 0.0f;           // 512 floats = both buffers
    uint32_t bar0 = (uint32_t)__cvta_generic_to_shared(&hbar[0]);
    uint32_t hb0  = (uint32_t)__cvta_generic_to_shared(&hbuf[0][0]);
    if (tid == 0) {
#pragma unroll
        for (int b = 0; b < 8; b++) mbar_init_(bar0 + b * 8, 1);
    }

    // hoisted remote addresses (barrier base and hbuf base per peer)
    uint32_t rd_h[WCLUSTER], rd_b[WCLUSTER];
#pragma unroll
    for (int r = 0; r < WCLUSTER; r++) {
        rd_h[r] = mapa_u32(hb0, r);
        rd_b[r] = mapa_u32(bar0, r);
    }

    bool tail = (w == 15);
    bool xduty = (ks2 == 0 && khalf == 0);   // one slice per gate row folds x
    float c = 0.0f;
    float xc = 0.f, xp = 0.f;
    if (xduty) {
        xc = __ldg(g_xg + grow);
        xp = __ldg(g_xg + (size_t)G_P + grow);
    }
    __syncthreads();
    cluster_sync_();   // barriers + hbuf init visible cluster-wide

    uint32_t slice_boff = (uint32_t)((rank >> 2) * 8);  // sender's target slice bar

    for (int n = 0; n < NWORDS; n++) {
        int p = n & 1;
        if (n > 0)   // wait only for THIS 64-wide k-slice's four source CTAs
            mbar_wait_parity_(bar0 + (uint32_t)((((n - 1) & 1) * 4 + ks2) * 8),
                              (uint32_t)(((n - 1) >> 1) & 1));
        if (tail && lane < 4 && n < NWORDS - 1)
            mbar_arrive_expect_(bar0 + (uint32_t)((p * 4 + lane) * 8), 256u);

        // issue prefetch for step n+2 (xduty threads)
        float xn = 0.f;
        if (xduty && n + 2 < NWORDS)
            xn = __ldg(g_xg + (size_t)(n + 2) * G_P + grow);

        // packed matvec: 4 accumulators (shorter dep chains)
        const ulonglong2* hp2 = (const ulonglong2*)(&hbuf[p][k0]);
        unsigned long long a0 = 0ull, a1 = 0ull, a2 = 0ull, a3 = 0ull;
#pragma unroll
        for (int i = 0; i < 4; i++) {
            ulonglong2 hvA = hp2[2 * i];
            ulonglong2 hvB = hp2[2 * i + 1];
            FMA_F32X2(a0, wreg[4 * i + 0], hvA.x);
            FMA_F32X2(a1, wreg[4 * i + 1], hvA.y);
            FMA_F32X2(a2, wreg[4 * i + 2], hvB.x);
            FMA_F32X2(a3, wreg[4 * i + 3], hvB.y);
        }
        {
            float l0, h0, l1, h1, l2, h2, l3, h3;
            UNPACK_F32X2(l0, h0, a0);
            UNPACK_F32X2(l1, h1, a1);
            UNPACK_F32X2(l2, h2, a2);
            UNPACK_F32X2(l3, h3, a3);
            float partial = ((l0 + h0) + (l1 + h1)) + ((l2 + h2) + (l3 + h3));
            if (xduty) { partial += xc; xc = xp; xp = xn; }
            ((float*)&pacc4[p][(s >> 2) * 64 + q * 16 + u])[s & 3] = partial;
        }

        if (!tail) {
            // producers: hand off and go straight to next step's slice wait
            asm volatile("bar.arrive 1, 512;" ::: "memory");
        } else {
            asm volatile("bar.sync 1, 512;" ::: "memory");
            // all 32 lanes compute unit u = lane&15 (duplicated across halves)
            float4 ga0 = pacc4[p][u];                // gate i, slices 0-3
            float4 gb0 = pacc4[p][64 + u];           // gate i, slices 4-7
            float4 ga1 = pacc4[p][16 + u];
            float4 gb1 = pacc4[p][80 + u];
            float4 ga2 = pacc4[p][32 + u];
            float4 gb2 = pacc4[p][96 + u];
            float4 ga3 = pacc4[p][48 + u];
            float4 gb3 = pacc4[p][112 + u];
            float s0 = ((ga0.x + ga0.y) + (ga0.z + ga0.w)) +
                       ((gb0.x + gb0.y) + (gb0.z + gb0.w));
            float s1 = ((ga1.x + ga1.y) + (ga1.z + ga1.w)) +
                       ((gb1.x + gb1.y) + (gb1.z + gb1.w));
            float s2 = ((ga2.x + ga2.y) + (ga2.z + ga2.w)) +
                       ((gb2.x + gb2.y) + (gb2.z + gb2.w));
            float s3 = ((ga3.x + ga3.y) + (ga3.z + ga3.w)) +
                       ((gb3.x + gb3.y) + (gb3.z + gb3.w));
            float iv = sig_mufu(s0);
            float fv = sig_mufu(s1);
            float gv = tanh_mufu(s2);
            float ov = sig_mufu(s3);
            c = fmaf(fv, c, iv * gv);
            float hn = ov * tanh_mufu(c);
            if (lane < 16)
                g_hs[(size_t)n * HP + rank * 16 + lane] = hn;

            if (n < NWORDS - 1) {
                // pair units -> 8B payloads; even lanes send.
                // half 0 (lanes 0-15 even) -> peers 0-7; half 1 -> peers 8-15.
                float pv = __shfl_xor_sync(0xffffffffu, hn, 1);
                if ((lane & 1) == 0) {
                    unsigned long long hv2;
                    asm("mov.b64 %0, {%1, %2};" : "=l"(hv2) : "f"(hn), "f"(pv));
                    uint32_t off = (uint32_t)((p ^ 1) * (HP * 4) + (rank * 16 + u) * 4);
                    uint32_t boff = (uint32_t)(p * 4 * 8) + slice_boff;
                    int rbase = khalf * 8;
#pragma unroll
                    for (int r = 0; r < 8; r++)
                        st_async_b64_(rd_h[rbase + r] + off, hv2,
                                      rd_b[rbase + r] + boff);
                }
            }
        }
    }
    cluster_sync_();   // no CTA exits while peers' st.async may be in flight
}

// ---------------------------------------------------------------------------
// Tag projection + log-softmax: one block (64 threads) per word
// ---------------------------------------------------------------------------
__global__ void __launch_bounds__(64)
tag_kernel(const float* __restrict__ W_tag,
           const float* __restrict__ b_tag,
           float* __restrict__ out) {
    __shared__ float hs[HP];
    __shared__ float vals[TAGS];
    __shared__ float red[2];

    int n = blockIdx.x;
    int t = threadIdx.x;
    *(float4*)(hs + t * 4) = *(const float4*)(g_hs + (size_t)n * HP + t * 4);
    __syncthreads();

    if (t < TAGS) {
        const float* wr = W_tag + t * HP;
        float a0 = b_tag[t], a1 = 0.0f, a2 = 0.0f, a3 = 0.0f;
#pragma unroll 8
        for (int k = 0; k < HP; k += 4) {
            float4 wv = *(const float4*)(wr + k);
            a0 = fmaf(wv.x, hs[k + 0], a0);
            a1 = fmaf(wv.y, hs[k + 1], a1);
            a2 = fmaf(wv.z, hs[k + 2], a2);
            a3 = fmaf(wv.w, hs[k + 3], a3);
        }
        vals[t] = (a0 + a1) + (a2 + a3);
    }
    __syncthreads();

    if (t < 32) {
        float m = vals[t];
        if (t + 32 < TAGS) m = fmaxf(m, vals[t + 32]);
#pragma unroll
        for (int o = 16; o > 0; o >>= 1)
            m = fmaxf(m, __shfl_xor_sync(0xffffffffu, m, o));
        float s = expf(vals[t] - m);
        if (t + 32 < TAGS) s += expf(vals[t + 32] - m);
#pragma unroll
        for (int o = 16; o > 0; o >>= 1)
            s += __shfl_xor_sync(0xffffffffu, s, o);
        if (t == 0) { red[0] = m; red[1] = logf(s); }
    }
    __syncthreads();

    if (t < TAGS) out[(size_t)n * TAGS + t] = vals[t] - red[0] - red[1];
}

// ---------------------------------------------------------------------------
// Launch
// ---------------------------------------------------------------------------
extern "C" void kernel_launch(void* const* d_in, const int* in_sizes, int n_in,
                              void* d_out, int out_size) {
    const float* char_emb = (const float*)d_in[0];
    const float* word_emb = (const float*)d_in[1];
    const float* Wih_e    = (const float*)d_in[2];
    const float* Whh_e    = (const float*)d_in[3];
    const float* bih_e    = (const float*)d_in[4];
    const float* bhh_e    = (const float*)d_in[5];
    const float* Wih_p    = (const float*)d_in[6];
    const float* Whh_p    = (const float*)d_in[7];
    const float* bih_p    = (const float*)d_in[8];
    const float* bhh_p    = (const float*)d_in[9];
    const float* W_tag    = (const float*)d_in[10];
    const float* b_tag    = (const float*)d_in[11];
    const int*   sentence = (const int*)d_in[12];
    const int*   char_ids = (const int*)d_in[13];
    const int*   char_len = (const int*)d_in[14];
    float* out = (float*)d_out;

    (void)in_sizes; (void)n_in; (void)out_size;

    cudaFuncSetAttribute(char_lstm_kernel,
                         cudaFuncAttributeMaxDynamicSharedMemorySize,
                         CHAR_SMEM_BYTES);
    cudaFuncSetAttribute(word_lstm_kernel,
                         cudaFuncAttributeNonPortableClusterSizeAllowed, 1);

    prep_table_kernel<<<256, 256>>>(char_emb, Wih_e, bih_e, bhh_e);
    prep_wte_kernel<<<256, 256>>>(Whh_e);
    prep_wpt_kernel<<<1536, 256>>>(Wih_p);

    char_lstm_kernel<<<128, 512, CHAR_SMEM_BYTES>>>(char_ids, char_len);

    xgates_kernel<<<dim3(16, 128), 256>>>(word_emb, sentence, bih_p, bhh_p);

    word_lstm_kernel<<<WCLUSTER, 512>>>(Whh_p);

    tag_kernel<<<NWORDS, 64>>>(W_tag, b_tag, out);
}

// round 15
// speedup vs baseline: 1.0262x; 1.0262x over previous
#include <cuda_runtime.h>
#include <cuda_bf16.h>
#include <math.h>
#include <stdint.h>

// ---------------------------------------------------------------------------
// Problem constants
// ---------------------------------------------------------------------------
#define CHAR_SIZE 128
#define CE        64
#define HE        128      // char LSTM hidden
#define WE        256
#define HP        256      // word LSTM hidden
#define TAGS      50
#define NWORDS    8192
#define MAXCH     16
#define G_E       (4*HE)   // 512
#define G_P       (4*HP)   // 1024
#define KIN_P     (WE+HE)  // 384
#define WCLUSTER  16       // word-LSTM cluster size (non-portable)

// ---------------------------------------------------------------------------
// Scratch (static device globals; no allocation allowed)
// ---------------------------------------------------------------------------
__device__ float g_tablep[CHAR_SIZE * G_E];      // [ch][u*4+q] char xgate table (+biases)
__device__ float g_WTe[HE * G_E];                // [k][u*4+q]  permuted Whh_e
__device__ float g_xg[(size_t)NWORDS * G_P];     // word-LSTM input gates (+biases)
__device__ float g_hchar[NWORDS * HE];           // char LSTM final hidden
__device__ float g_hs[NWORDS * HP];              // word LSTM hidden states

// ---------------------------------------------------------------------------
// Packed f32x2 helpers (Blackwell: fma.rn.f32x2 only reachable via PTX)
// ---------------------------------------------------------------------------
#define FMA_F32X2(acc, a, b) \
    asm("fma.rn.f32x2 %0, %1, %2, %0;" : "+l"(acc) : "l"(a), "l"(b))
#define SPLAT_F32X2(out, f) \
    asm("mov.b64 %0, {%1, %1};" : "=l"(out) : "f"(f))
#define UNPACK_F32X2(lo, hi, v) \
    asm("mov.b64 {%0, %1}, %2;" : "=f"(lo), "=f"(hi) : "l"(v))

// ---------------------------------------------------------------------------
// Fast activations (char/tag path)
// ---------------------------------------------------------------------------
__device__ __forceinline__ float sigf(float x) {
    return __fdividef(1.0f, 1.0f + __expf(-x));
}
__device__ __forceinline__ float tanhfast(float x) {
    x = fminf(9.0f, fmaxf(-9.0f, x));
    float e = __expf(-2.0f * x);
    return __fdividef(1.0f - e, 1.0f + e);
}
// MUFU tanh path (word-LSTM tail only)
__device__ __forceinline__ float tanh_mufu(float x) {
    float r;
    asm("tanh.approx.f32 %0, %1;" : "=f"(r) : "f"(x));
    return r;
}
__device__ __forceinline__ float sig_mufu(float x) {
    float r;
    asm("tanh.approx.f32 %0, %1;" : "=f"(r) : "f"(0.5f * x));
    return fmaf(0.5f, r, 0.5f);
}

// ---------------------------------------------------------------------------
// Prep kernels
// ---------------------------------------------------------------------------
__global__ void prep_table_kernel(const float* __restrict__ char_emb,
                                  const float* __restrict__ Wih_e,
                                  const float* __restrict__ bih_e,
                                  const float* __restrict__ bhh_e) {
    int idx = blockIdx.x * 256 + threadIdx.x;        // 0 .. 128*512-1
    int ch = idx >> 9;
    int col = idx & 511;
    int u = col >> 2, q = col & 3;
    int row = q * HE + u;
    float acc = bih_e[row] + bhh_e[row];
    const float* ce = char_emb + ch * CE;
    const float* wr = Wih_e + row * CE;
#pragma unroll 16
    for (int k = 0; k < CE; k++) acc = fmaf(ce[k], wr[k], acc);
    g_tablep[idx] = acc;
}

__global__ void prep_wte_kernel(const float* __restrict__ Whh_e) {
    int idx = blockIdx.x * 256 + threadIdx.x;
    int k = idx >> 9;
    int col = idx & 511;
    int u = col >> 2, q = col & 3;
    g_WTe[idx] = Whh_e[(q * HE + u) * HE + k];
}

// ---------------------------------------------------------------------------
// Char LSTM: 128 blocks x 512 threads, 64 words per block. (round-8 proven)
// ---------------------------------------------------------------------------
#define CHAR_SMEM_BYTES ((8192 + 8192 + 16384 + 128) * 4)

__global__ void __launch_bounds__(512, 1)
char_lstm_kernel(const int* __restrict__ char_ids,
                 const int* __restrict__ char_lengths) {
    extern __shared__ __align__(16) float sm[];
    float* hA = sm;                         // [128][64]
    float* hB = sm + 8192;                  // [128][64]
    float* wt = sm + 16384;                 // [128][128]
    int*   lens = (int*)(sm + 32768);       // [64]
    int*   chs  = (int*)(sm + 32768 + 64);  // [64]

    int tid = threadIdx.x;
    int wbase = blockIdx.x * 64;
    int sub = tid >> 8;          // 0/1 (uniform per warp)
    int stid = tid & 255;
    int w0 = (stid & 15) * 4;    // words w0..w0+3
    int ug = stid >> 4;          // 0..15

    for (int i = tid; i < 8192; i += 512) hA[i] = 0.0f;
    if (tid < 64) lens[tid] = char_lengths[wbase + tid];
    __syncthreads();

    int len4[4];
#pragma unroll
    for (int j = 0; j < 4; j++) len4[j] = lens[w0 + j];

    float c_reg[16];             // cells: 4 uc2-chunks x 4 words
#pragma unroll
    for (int i = 0; i < 16; i++) c_reg[i] = 0.0f;

    for (int t = 0; t < MAXCH; t++) {
        if (tid < 64) chs[tid] = char_ids[(wbase + tid) * MAXCH + t];
        __syncthreads();
        float* hc = (t & 1) ? hB : hA;
        float* hn = (t & 1) ? hA : hB;

        for (int uc2 = 0; uc2 < 4; uc2++) {
            int u = (uc2 * 2 + sub) * 16 + ug;   // unit 0..127

            float4 tb[4];
#pragma unroll
            for (int j = 0; j < 4; j++)
                tb[j] = *(const float4*)(g_tablep + chs[w0 + j] * G_E + u * 4);

#pragma unroll
            for (int j = 0; j < 8; j++) {
                int lin = tid + 512 * j;          // 0..4095 float4 slots
                int k = lin >> 5;
                int c4 = lin & 31;
                *(float4*)(wt + k * 128 + c4 * 4) =
                    *(const float4*)(g_WTe + k * G_E + uc2 * 128 + c4 * 4);
            }
            __syncthreads();

            unsigned long long acc2[2][4];
#pragma unroll
            for (int a = 0; a < 2; a++)
#pragma unroll
                for (int b = 0; b < 4; b++) acc2[a][b] = 0ull;

#pragma unroll 4
            for (int k = 0; k < HE; k++) {
                float4 b = *(const float4*)(wt + k * 128 + sub * 64 + ug * 4);
                ulonglong2 av = *(const ulonglong2*)(hc + k * 64 + w0);
                unsigned long long bx, by, bz, bw;
                SPLAT_F32X2(bx, b.x);
                SPLAT_F32X2(by, b.y);
                SPLAT_F32X2(bz, b.z);
                SPLAT_F32X2(bw, b.w);
                FMA_F32X2(acc2[0][0], av.x, bx);
                FMA_F32X2(acc2[0][1], av.x, by);
                FMA_F32X2(acc2[0][2], av.x, bz);
                FMA_F32X2(acc2[0][3], av.x, bw);
                FMA_F32X2(acc2[1][0], av.y, bx);
                FMA_F32X2(acc2[1][1], av.y, by);
                FMA_F32X2(acc2[1][2], av.y, bz);
                FMA_F32X2(acc2[1][3], av.y, bw);
            }

            float accf[4][4];
#pragma unroll
            for (int rp = 0; rp < 2; rp++)
#pragma unroll
                for (int cx = 0; cx < 4; cx++)
                    UNPACK_F32X2(accf[2 * rp][cx], accf[2 * rp + 1][cx], acc2[rp][cx]);

            float4 hold = *(const float4*)(hc + u * 64 + w0);
            float hv[4] = {hold.x, hold.y, hold.z, hold.w};
            float hnv[4];
#pragma unroll
            for (int j = 0; j < 4; j++) {
                float pi = accf[j][0] + tb[j].x;
                float pf = accf[j][1] + tb[j].y;
                float pg = accf[j][2] + tb[j].z;
                float po = accf[j][3] + tb[j].w;
                float iv = sigf(pi), fv = sigf(pf);
                float gv = tanhfast(pg), ov = sigf(po);
                float cold = c_reg[uc2 * 4 + j];
                float cn = fmaf(fv, cold, iv * gv);
                float hh = ov * tanhfast(cn);
                bool msk = (t < len4[j]);
                c_reg[uc2 * 4 + j] = msk ? cn : cold;
                hnv[j] = msk ? hh : hv[j];
            }
            float4 outv;
            outv.x = hnv[0]; outv.y = hnv[1]; outv.z = hnv[2]; outv.w = hnv[3];
            *(float4*)(hn + u * 64 + w0) = outv;
            __syncthreads();
        }
    }

#pragma unroll
    for (int uc2 = 0; uc2 < 4; uc2++) {
        int u = (uc2 * 2 + sub) * 16 + ug;
        float4 hv = *(const float4*)(hA + u * 64 + w0);
        g_hchar[(wbase + w0 + 0) * HE + u] = hv.x;
        g_hchar[(wbase + w0 + 1) * HE + u] = hv.y;
        g_hchar[(wbase + w0 + 2) * HE + u] = hv.z;
        g_hchar[(wbase + w0 + 3) * HE + u] = hv.w;
    }
}

// ---------------------------------------------------------------------------
// Word-LSTM input gates (NEW packed-k f32x2):
//   xg[n][g] = feats[n] @ Wih_p.T + bih_p + bhh_p
// As:  [64 n][66-pad k] (8B-aligned k-pairs; broadcast reads)
// Bs2: [64 g][66-pad k] loaded straight from Wih_p (native [g][k])
// Inner: per k-pair 8 x LDS.64 + 16 x FFMA2 (vs 10 LDS + 32 FFMA scalar).
// ---------------------------------------------------------------------------
__global__ void __launch_bounds__(256)
xgates_kernel(const float* __restrict__ word_emb,
              const float* __restrict__ Wih_p,
              const int* __restrict__ sentence,
              const float* __restrict__ bih_p,
              const float* __restrict__ bhh_p) {
    __shared__ __align__(16) float As[64 * 66];
    __shared__ __align__(16) float Bs2[64 * 66];
    __shared__ int sent[64];

    int bg = blockIdx.x;   // 0..15  (gate-column tile)
    int bn = blockIdx.y;   // 0..127 (word tile)
    int tid = threadIdx.x;
    if (tid < 64) sent[tid] = sentence[bn * 64 + tid];

    int n0 = (tid >> 4) << 2;      // word base 0..60
    int g0 = (tid & 15) << 2;      // gate base 0..60 (within tile)

    unsigned long long acc2[4][4];
#pragma unroll
    for (int a = 0; a < 4; a++)
#pragma unroll
        for (int b = 0; b < 4; b++) acc2[a][b] = 0ull;

    for (int kc = 0; kc < 6; kc++) {
        __syncthreads();
#pragma unroll
        for (int j = 0; j < 16; j++) {
            int lin = tid + 256 * j;                 // 0..4095
            int row = lin >> 6;                      // n (for As) / g (for Bs2)
            int k = lin & 63;
            int kk = kc * 64 + k;
            float v;
            if (kk < WE) v = word_emb[(size_t)sent[row] * WE + kk];
            else         v = g_hchar[(bn * 64 + row) * HE + (kk - WE)];
            As[row * 66 + k] = v;
            Bs2[row * 66 + k] =
                Wih_p[(size_t)(bg * 64 + row) * KIN_P + kk];
        }
        __syncthreads();

#pragma unroll 8
        for (int kp = 0; kp < 32; kp++) {
            unsigned long long b0 = *(const unsigned long long*)(Bs2 + (g0 + 0) * 66 + 2 * kp);
            unsigned long long b1 = *(const unsigned long long*)(Bs2 + (g0 + 1) * 66 + 2 * kp);
            unsigned long long b2 = *(const unsigned long long*)(Bs2 + (g0 + 2) * 66 + 2 * kp);
            unsigned long long b3 = *(const unsigned long long*)(Bs2 + (g0 + 3) * 66 + 2 * kp);
            unsigned long long a0 = *(const unsigned long long*)(As + (n0 + 0) * 66 + 2 * kp);
            unsigned long long a1 = *(const unsigned long long*)(As + (n0 + 1) * 66 + 2 * kp);
            unsigned long long a2 = *(const unsigned long long*)(As + (n0 + 2) * 66 + 2 * kp);
            unsigned long long a3 = *(const unsigned long long*)(As + (n0 + 3) * 66 + 2 * kp);
            FMA_F32X2(acc2[0][0], a0, b0);
            FMA_F32X2(acc2[0][1], a0, b1);
            FMA_F32X2(acc2[0][2], a0, b2);
            FMA_F32X2(acc2[0][3], a0, b3);
            FMA_F32X2(acc2[1][0], a1, b0);
            FMA_F32X2(acc2[1][1], a1, b1);
            FMA_F32X2(acc2[1][2], a1, b2);
            FMA_F32X2(acc2[1][3], a1, b3);
            FMA_F32X2(acc2[2][0], a2, b0);
            FMA_F32X2(acc2[2][1], a2, b1);
            FMA_F32X2(acc2[2][2], a2, b2);
            FMA_F32X2(acc2[2][3], a2, b3);
            FMA_F32X2(acc2[3][0], a3, b0);
            FMA_F32X2(acc2[3][1], a3, b1);
            FMA_F32X2(acc2[3][2], a3, b2);
            FMA_F32X2(acc2[3][3], a3, b3);
        }
    }

    int ggl = bg * 64 + g0;
    float4 bi = *(const float4*)(bih_p + ggl);
    float4 bh = *(const float4*)(bhh_p + ggl);
#pragma unroll
    for (int l = 0; l < 4; l++) {
        float lo0, hi0, lo1, hi1, lo2, hi2, lo3, hi3;
        UNPACK_F32X2(lo0, hi0, acc2[l][0]);
        UNPACK_F32X2(lo1, hi1, acc2[l][1]);
        UNPACK_F32X2(lo2, hi2, acc2[l][2]);
        UNPACK_F32X2(lo3, hi3, acc2[l][3]);
        float4 o;
        o.x = (lo0 + hi0) + bi.x + bh.x;
        o.y = (lo1 + hi1) + bi.y + bh.y;
        o.z = (lo2 + hi2) + bi.z + bh.z;
        o.w = (lo3 + hi3) + bi.w + bh.w;
        *(float4*)(g_xg + (size_t)(bn * 64 + n0 + l) * G_P + ggl) = o;
    }
}

// ---------------------------------------------------------------------------
// Word LSTM: 16-CTA non-portable cluster (round-14, measured-neutral best),
// packed f32x2 matvec, st.async.b64 broadcast, 4 per-k-slice mbarriers,
// MUFU activations, acquire.cta wait, 4-accumulator matvec.
// ---------------------------------------------------------------------------
__device__ __forceinline__ uint32_t cluster_rank_() {
    uint32_t r;
    asm("mov.u32 %0, %%cluster_ctarank;" : "=r"(r));
    return r;
}
__device__ __forceinline__ void cluster_sync_() {
    asm volatile("barrier.cluster.arrive.aligned;" ::: "memory");
    asm volatile("barrier.cluster.wait.aligned;" ::: "memory");
}
__device__ __forceinline__ uint32_t mapa_u32(uint32_t la, int r) {
    uint32_t ra;
    asm("mapa.shared::cluster.u32 %0, %1, %2;" : "=r"(ra) : "r"(la), "r"(r));
    return ra;
}
__device__ __forceinline__ void mbar_init_(uint32_t bar, uint32_t cnt) {
    asm volatile("mbarrier.init.shared.b64 [%0], %1;" :: "r"(bar), "r"(cnt) : "memory");
}
__device__ __forceinline__ void mbar_arrive_expect_(uint32_t bar, uint32_t bytes) {
    asm volatile("mbarrier.arrive.expect_tx.shared.b64 _, [%0], %1;"
                 :: "r"(bar), "r"(bytes) : "memory");
}
__device__ __forceinline__ void mbar_wait_parity_(uint32_t bar, uint32_t ph) {
    asm volatile(
        "{\n\t"
        ".reg .pred P1;\n\t"
        "WL_%=:\n\t"
        "mbarrier.try_wait.parity.acquire.cta.shared::cta.b64 P1, [%0], %1, 0x989680;\n\t"
        "@P1 bra.uni WD_%=;\n\t"
        "bra.uni WL_%=;\n\t"
        "WD_%=:\n\t"
        "}"
        :: "r"(bar), "r"(ph) : "memory");
}
__device__ __forceinline__ void st_async_b64_(uint32_t raddr, unsigned long long v,
                                              uint32_t rbar) {
    asm volatile(
        "st.async.shared::cluster.mbarrier::complete_tx::bytes.b64 [%0], %1, [%2];"
        :: "r"(raddr), "l"(v), "r"(rbar) : "memory");
}

__global__ void __launch_bounds__(512, 1) __cluster_dims__(WCLUSTER, 1, 1)
word_lstm_kernel(const float* __restrict__ Whh_p) {
    __shared__ __align__(16) float hbuf[2][HP];      // h double-buffer
    __shared__ __align__(16) float4 pacc4[2][128];
    __shared__ __align__(8) unsigned long long hbar[8];  // [parity*4 + slice64]

    int rank = (int)cluster_rank_();
    int tid = threadIdx.x;
    int w = tid >> 5, lane = tid & 31;
    int q = w & 3;                        // gate quadrant
    int ks2 = w >> 2;                     // 64-wide k-slice 0..3
    int u = lane & 15;                    // unit within CTA
    int khalf = lane >> 4;                // 32-wide half within slice
    int s = ks2 * 2 + khalf;              // 32-wide k-slice 0..7
    int grow = q * HP + rank * 16 + u;    // global gate row 0..1023
    int k0 = ks2 * 64 + khalf * 32;       // this thread's k range [k0, k0+32)

    unsigned long long wreg[16];
    {
        const float* wp = Whh_p + (size_t)grow * HP + k0;
#pragma unroll
        for (int i = 0; i < 8; i++) {
            ulonglong2 v = *(const ulonglong2*)(wp + i * 4);
            wreg[2 * i] = v.x;
            wreg[2 * i + 1] = v.y;
        }
    }

    ((float*)hbuf)[tid] = 0.0f;           // 512 floats = both buffers
    uint32_t bar0 = (uint32_t)__cvta_generic_to_shared(&hbar[0]);
    uint32_t hb0  = (uint32_t)__cvta_generic_to_shared(&hbuf[0][0]);
    if (tid == 0) {
#pragma unroll
        for (int b = 0; b < 8; b++) mbar_init_(bar0 + b * 8, 1);
    }

    uint32_t rd_h[WCLUSTER], rd_b[WCLUSTER];
#pragma unroll
    for (int r = 0; r < WCLUSTER; r++) {
        rd_h[r] = mapa_u32(hb0, r);
        rd_b[r] = mapa_u32(bar0, r);
    }

    bool tail = (w == 15);
    bool xduty = (ks2 == 0 && khalf == 0);
    float c = 0.0f;
    float xc = 0.f, xp = 0.f;
    if (xduty) {
        xc = __ldg(g_xg + grow);
        xp = __ldg(g_xg + (size_t)G_P + grow);
    }
    __syncthreads();
    cluster_sync_();

    uint32_t slice_boff = (uint32_t)((rank >> 2) * 8);

    for (int n = 0; n < NWORDS; n++) {
        int p = n & 1;
        if (n > 0)
            mbar_wait_parity_(bar0 + (uint32_t)((((n - 1) & 1) * 4 + ks2) * 8),
                              (uint32_t)(((n - 1) >> 1) & 1));
        if (tail && lane < 4 && n < NWORDS - 1)
            mbar_arrive_expect_(bar0 + (uint32_t)((p * 4 + lane) * 8), 256u);

        float xn = 0.f;
        if (xduty && n + 2 < NWORDS)
            xn = __ldg(g_xg + (size_t)(n + 2) * G_P + grow);

        const ulonglong2* hp2 = (const ulonglong2*)(&hbuf[p][k0]);
        unsigned long long a0 = 0ull, a1 = 0ull, a2 = 0ull, a3 = 0ull;
#pragma unroll
        for (int i = 0; i < 4; i++) {
            ulonglong2 hvA = hp2[2 * i];
            ulonglong2 hvB = hp2[2 * i + 1];
            FMA_F32X2(a0, wreg[4 * i + 0], hvA.x);
            FMA_F32X2(a1, wreg[4 * i + 1], hvA.y);
            FMA_F32X2(a2, wreg[4 * i + 2], hvB.x);
            FMA_F32X2(a3, wreg[4 * i + 3], hvB.y);
        }
        {
            float l0, h0, l1, h1, l2, h2, l3, h3;
            UNPACK_F32X2(l0, h0, a0);
            UNPACK_F32X2(l1, h1, a1);
            UNPACK_F32X2(l2, h2, a2);
            UNPACK_F32X2(l3, h3, a3);
            float partial = ((l0 + h0) + (l1 + h1)) + ((l2 + h2) + (l3 + h3));
            if (xduty) { partial += xc; xc = xp; xp = xn; }
            ((float*)&pacc4[p][(s >> 2) * 64 + q * 16 + u])[s & 3] = partial;
        }

        if (!tail) {
            asm volatile("bar.arrive 1, 512;" ::: "memory");
        } else {
            asm volatile("bar.sync 1, 512;" ::: "memory");
            float4 ga0 = pacc4[p][u];
            float4 gb0 = pacc4[p][64 + u];
            float4 ga1 = pacc4[p][16 + u];
            float4 gb1 = pacc4[p][80 + u];
            float4 ga2 = pacc4[p][32 + u];
            float4 gb2 = pacc4[p][96 + u];
            float4 ga3 = pacc4[p][48 + u];
            float4 gb3 = pacc4[p][112 + u];
            float s0 = ((ga0.x + ga0.y) + (ga0.z + ga0.w)) +
                       ((gb0.x + gb0.y) + (gb0.z + gb0.w));
            float s1 = ((ga1.x + ga1.y) + (ga1.z + ga1.w)) +
                       ((gb1.x + gb1.y) + (gb1.z + gb1.w));
            float s2 = ((ga2.x + ga2.y) + (ga2.z + ga2.w)) +
                       ((gb2.x + gb2.y) + (gb2.z + gb2.w));
            float s3 = ((ga3.x + ga3.y) + (ga3.z + ga3.w)) +
                       ((gb3.x + gb3.y) + (gb3.z + gb3.w));
            float iv = sig_mufu(s0);
            float fv = sig_mufu(s1);
            float gv = tanh_mufu(s2);
            float ov = sig_mufu(s3);
            c = fmaf(fv, c, iv * gv);
            float hn = ov * tanh_mufu(c);
            if (lane < 16)
                g_hs[(size_t)n * HP + rank * 16 + lane] = hn;

            if (n < NWORDS - 1) {
                float pv = __shfl_xor_sync(0xffffffffu, hn, 1);
                if ((lane & 1) == 0) {
                    unsigned long long hv2;
                    asm("mov.b64 %0, {%1, %2};" : "=l"(hv2) : "f"(hn), "f"(pv));
                    uint32_t off = (uint32_t)((p ^ 1) * (HP * 4) + (rank * 16 + u) * 4);
                    uint32_t boff = (uint32_t)(p * 4 * 8) + slice_boff;
                    int rbase = khalf * 8;
#pragma unroll
                    for (int r = 0; r < 8; r++)
                        st_async_b64_(rd_h[rbase + r] + off, hv2,
                                      rd_b[rbase + r] + boff);
                }
            }
        }
    }
    cluster_sync_();
}

// ---------------------------------------------------------------------------
// Tag projection + log-softmax: one block (64 threads) per word
// ---------------------------------------------------------------------------
__global__ void __launch_bounds__(64)
tag_kernel(const float* __restrict__ W_tag,
           const float* __restrict__ b_tag,
           float* __restrict__ out) {
    __shared__ float hs[HP];
    __shared__ float vals[TAGS];
    __shared__ float red[2];

    int n = blockIdx.x;
    int t = threadIdx.x;
    *(float4*)(hs + t * 4) = *(const float4*)(g_hs + (size_t)n * HP + t * 4);
    __syncthreads();

    if (t < TAGS) {
        const float* wr = W_tag + t * HP;
        float a0 = b_tag[t], a1 = 0.0f, a2 = 0.0f, a3 = 0.0f;
#pragma unroll 8
        for (int k = 0; k < HP; k += 4) {
            float4 wv = *(const float4*)(wr + k);
            a0 = fmaf(wv.x, hs[k + 0], a0);
            a1 = fmaf(wv.y, hs[k + 1], a1);
            a2 = fmaf(wv.z, hs[k + 2], a2);
            a3 = fmaf(wv.w, hs[k + 3], a3);
        }
        vals[t] = (a0 + a1) + (a2 + a3);
    }
    __syncthreads();

    if (t < 32) {
        float m = vals[t];
        if (t + 32 < TAGS) m = fmaxf(m, vals[t + 32]);
#pragma unroll
        for (int o = 16; o > 0; o >>= 1)
            m = fmaxf(m, __shfl_xor_sync(0xffffffffu, m, o));
        float s = expf(vals[t] - m);
        if (t + 32 < TAGS) s += expf(vals[t + 32] - m);
#pragma unroll
        for (int o = 16; o > 0; o >>= 1)
            s += __shfl_xor_sync(0xffffffffu, s, o);
        if (t == 0) { red[0] = m; red[1] = logf(s); }
    }
    __syncthreads();

    if (t < TAGS) out[(size_t)n * TAGS + t] = vals[t] - red[0] - red[1];
}

// ---------------------------------------------------------------------------
// Launch
// ---------------------------------------------------------------------------
extern "C" void kernel_launch(void* const* d_in, const int* in_sizes, int n_in,
                              void* d_out, int out_size) {
    const float* char_emb = (const float*)d_in[0];
    const float* word_emb = (const float*)d_in[1];
    const float* Wih_e    = (const float*)d_in[2];
    const float* Whh_e    = (const float*)d_in[3];
    const float* bih_e    = (const float*)d_in[4];
    const float* bhh_e    = (const float*)d_in[5];
    const float* Wih_p    = (const float*)d_in[6];
    const float* Whh_p    = (const float*)d_in[7];
    const float* bih_p    = (const float*)d_in[8];
    const float* bhh_p    = (const float*)d_in[9];
    const float* W_tag    = (const float*)d_in[10];
    const float* b_tag    = (const float*)d_in[11];
    const int*   sentence = (const int*)d_in[12];
    const int*   char_ids = (const int*)d_in[13];
    const int*   char_len = (const int*)d_in[14];
    float* out = (float*)d_out;

    (void)in_sizes; (void)n_in; (void)out_size;

    cudaFuncSetAttribute(char_lstm_kernel,
                         cudaFuncAttributeMaxDynamicSharedMemorySize,
                         CHAR_SMEM_BYTES);
    cudaFuncSetAttribute(word_lstm_kernel,
                         cudaFuncAttributeNonPortableClusterSizeAllowed, 1);

    prep_table_kernel<<<256, 256>>>(char_emb, Wih_e, bih_e, bhh_e);
    prep_wte_kernel<<<256, 256>>>(Whh_e);

    char_lstm_kernel<<<128, 512, CHAR_SMEM_BYTES>>>(char_ids, char_len);

    xgates_kernel<<<dim3(16, 128), 256>>>(word_emb, Wih_p, sentence,
                                          bih_p, bhh_p);

    word_lstm_kernel<<<WCLUSTER, 512>>>(Whh_p);

    tag_kernel<<<NWORDS, 64>>>(W_tag, b_tag, out);
}

// round 16
// speedup vs baseline: 1.0555x; 1.0286x over previous
#include <cuda_runtime.h>
#include <cuda_bf16.h>
#include <math.h>
#include <stdint.h>

// ---------------------------------------------------------------------------
// Problem constants
// ---------------------------------------------------------------------------
#define CHAR_SIZE 128
#define CE        64
#define HE        128      // char LSTM hidden
#define WE        256
#define HP        256      // word LSTM hidden
#define TAGS      50
#define NWORDS    8192
#define MAXCH     16
#define G_E       (4*HE)   // 512
#define G_P       (4*HP)   // 1024
#define KIN_P     (WE+HE)  // 384
#define WCLUSTER  16       // word-LSTM cluster size (non-portable)

// ---------------------------------------------------------------------------
// Scratch (static device globals; no allocation allowed)
// ---------------------------------------------------------------------------
__device__ float g_tablep[CHAR_SIZE * G_E];      // [ch][u*4+q] char xgate table (+biases)
__device__ float g_WTe[HE * G_E];                // [k][u*4+q]  permuted Whh_e
__device__ float g_WpT[KIN_P * G_P];             // [k][g]      transposed Wih_p
__device__ float g_featsT[(size_t)KIN_P * NWORDS]; // [k][n] transposed features
__device__ float g_xg[(size_t)NWORDS * G_P];     // word-LSTM input gates (+biases)
__device__ float g_hchar[NWORDS * HE];           // char LSTM final hidden
__device__ float g_hs[NWORDS * HP];              // word LSTM hidden states

// ---------------------------------------------------------------------------
// Packed f32x2 helpers (Blackwell: fma.rn.f32x2 only reachable via PTX)
// ---------------------------------------------------------------------------
#define FMA_F32X2(acc, a, b) \
    asm("fma.rn.f32x2 %0, %1, %2, %0;" : "+l"(acc) : "l"(a), "l"(b))
#define SPLAT_F32X2(out, f) \
    asm("mov.b64 %0, {%1, %1};" : "=l"(out) : "f"(f))
#define UNPACK_F32X2(lo, hi, v) \
    asm("mov.b64 {%0, %1}, %2;" : "=f"(lo), "=f"(hi) : "l"(v))

// ---------------------------------------------------------------------------
// Fast activations (char/tag path)
// ---------------------------------------------------------------------------
__device__ __forceinline__ float sigf(float x) {
    return __fdividef(1.0f, 1.0f + __expf(-x));
}
__device__ __forceinline__ float tanhfast(float x) {
    x = fminf(9.0f, fmaxf(-9.0f, x));
    float e = __expf(-2.0f * x);
    return __fdividef(1.0f - e, 1.0f + e);
}
// MUFU tanh path (word-LSTM tail only)
__device__ __forceinline__ float tanh_mufu(float x) {
    float r;
    asm("tanh.approx.f32 %0, %1;" : "=f"(r) : "f"(x));
    return r;
}
__device__ __forceinline__ float sig_mufu(float x) {
    float r;
    asm("tanh.approx.f32 %0, %1;" : "=f"(r) : "f"(0.5f * x));
    return fmaf(0.5f, r, 0.5f);
}

// ---------------------------------------------------------------------------
// Prep kernels
// ---------------------------------------------------------------------------
__global__ void prep_table_kernel(const float* __restrict__ char_emb,
                                  const float* __restrict__ Wih_e,
                                  const float* __restrict__ bih_e,
                                  const float* __restrict__ bhh_e) {
    int idx = blockIdx.x * 256 + threadIdx.x;        // 0 .. 128*512-1
    int ch = idx >> 9;
    int col = idx & 511;
    int u = col >> 2, q = col & 3;
    int row = q * HE + u;
    float acc = bih_e[row] + bhh_e[row];
    const float* ce = char_emb + ch * CE;
    const float* wr = Wih_e + row * CE;
#pragma unroll 16
    for (int k = 0; k < CE; k++) acc = fmaf(ce[k], wr[k], acc);
    g_tablep[idx] = acc;
}

__global__ void prep_wte_kernel(const float* __restrict__ Whh_e) {
    int idx = blockIdx.x * 256 + threadIdx.x;
    int k = idx >> 9;
    int col = idx & 511;
    int u = col >> 2, q = col & 3;
    g_WTe[idx] = Whh_e[(q * HE + u) * HE + k];
}

__global__ void prep_wpt_kernel(const float* __restrict__ Wih_p) {
    int idx = blockIdx.x * 256 + threadIdx.x;        // 0 .. 384*1024-1
    int k = idx >> 10;
    int g = idx & 1023;
    g_WpT[idx] = Wih_p[g * KIN_P + k];
}

// feats transpose: g_featsT[k][n] = (k<WE) ? word_emb[sent[n]][k]
//                                          : g_hchar[n][k-WE]
// grid (256 n-tiles, 12 k-tiles), block (32,8); 32x32 smem tiles.
__global__ void __launch_bounds__(256)
feats_transpose_kernel(const float* __restrict__ word_emb,
                       const int* __restrict__ sentence) {
    __shared__ float tile[32][33];
    int n0 = blockIdx.x * 32;
    int k0 = blockIdx.y * 32;
    int tx = threadIdx.x, ty = threadIdx.y;

#pragma unroll
    for (int j = 0; j < 4; j++) {
        int n = n0 + ty + j * 8;
        int k = k0 + tx;
        float v;
        if (k < WE) v = word_emb[(size_t)sentence[n] * WE + k];
        else        v = g_hchar[n * HE + (k - WE)];
        tile[ty + j * 8][tx] = v;
    }
    __syncthreads();
#pragma unroll
    for (int j = 0; j < 4; j++) {
        int k = k0 + ty + j * 8;
        int n = n0 + tx;
        g_featsT[(size_t)k * NWORDS + n] = tile[tx][ty + j * 8];
    }
}

// ---------------------------------------------------------------------------
// Char LSTM: 128 blocks x 512 threads, 64 words per block. (round-8 proven)
// ---------------------------------------------------------------------------
#define CHAR_SMEM_BYTES ((8192 + 8192 + 16384 + 128) * 4)

__global__ void __launch_bounds__(512, 1)
char_lstm_kernel(const int* __restrict__ char_ids,
                 const int* __restrict__ char_lengths) {
    extern __shared__ __align__(16) float sm[];
    float* hA = sm;                         // [128][64]
    float* hB = sm + 8192;                  // [128][64]
    float* wt = sm + 16384;                 // [128][128]
    int*   lens = (int*)(sm + 32768);       // [64]
    int*   chs  = (int*)(sm + 32768 + 64);  // [64]

    int tid = threadIdx.x;
    int wbase = blockIdx.x * 64;
    int sub = tid >> 8;          // 0/1 (uniform per warp)
    int stid = tid & 255;
    int w0 = (stid & 15) * 4;    // words w0..w0+3
    int ug = stid >> 4;          // 0..15

    for (int i = tid; i < 8192; i += 512) hA[i] = 0.0f;
    if (tid < 64) lens[tid] = char_lengths[wbase + tid];
    __syncthreads();

    int len4[4];
#pragma unroll
    for (int j = 0; j < 4; j++) len4[j] = lens[w0 + j];

    float c_reg[16];             // cells: 4 uc2-chunks x 4 words
#pragma unroll
    for (int i = 0; i < 16; i++) c_reg[i] = 0.0f;

    for (int t = 0; t < MAXCH; t++) {
        if (tid < 64) chs[tid] = char_ids[(wbase + tid) * MAXCH + t];
        __syncthreads();
        float* hc = (t & 1) ? hB : hA;
        float* hn = (t & 1) ? hA : hB;

        for (int uc2 = 0; uc2 < 4; uc2++) {
            int u = (uc2 * 2 + sub) * 16 + ug;   // unit 0..127

            float4 tb[4];
#pragma unroll
            for (int j = 0; j < 4; j++)
                tb[j] = *(const float4*)(g_tablep + chs[w0 + j] * G_E + u * 4);

#pragma unroll
            for (int j = 0; j < 8; j++) {
                int lin = tid + 512 * j;          // 0..4095 float4 slots
                int k = lin >> 5;
                int c4 = lin & 31;
                *(float4*)(wt + k * 128 + c4 * 4) =
                    *(const float4*)(g_WTe + k * G_E + uc2 * 128 + c4 * 4);
            }
            __syncthreads();

            unsigned long long acc2[2][4];
#pragma unroll
            for (int a = 0; a < 2; a++)
#pragma unroll
                for (int b = 0; b < 4; b++) acc2[a][b] = 0ull;

#pragma unroll 4
            for (int k = 0; k < HE; k++) {
                float4 b = *(const float4*)(wt + k * 128 + sub * 64 + ug * 4);
                ulonglong2 av = *(const ulonglong2*)(hc + k * 64 + w0);
                unsigned long long bx, by, bz, bw;
                SPLAT_F32X2(bx, b.x);
                SPLAT_F32X2(by, b.y);
                SPLAT_F32X2(bz, b.z);
                SPLAT_F32X2(bw, b.w);
                FMA_F32X2(acc2[0][0], av.x, bx);
                FMA_F32X2(acc2[0][1], av.x, by);
                FMA_F32X2(acc2[0][2], av.x, bz);
                FMA_F32X2(acc2[0][3], av.x, bw);
                FMA_F32X2(acc2[1][0], av.y, bx);
                FMA_F32X2(acc2[1][1], av.y, by);
                FMA_F32X2(acc2[1][2], av.y, bz);
                FMA_F32X2(acc2[1][3], av.y, bw);
            }

            float accf[4][4];
#pragma unroll
            for (int rp = 0; rp < 2; rp++)
#pragma unroll
                for (int cx = 0; cx < 4; cx++)
                    UNPACK_F32X2(accf[2 * rp][cx], accf[2 * rp + 1][cx], acc2[rp][cx]);

            float4 hold = *(const float4*)(hc + u * 64 + w0);
            float hv[4] = {hold.x, hold.y, hold.z, hold.w};
            float hnv[4];
#pragma unroll
            for (int j = 0; j < 4; j++) {
                float pi = accf[j][0] + tb[j].x;
                float pf = accf[j][1] + tb[j].y;
                float pg = accf[j][2] + tb[j].z;
                float po = accf[j][3] + tb[j].w;
                float iv = sigf(pi), fv = sigf(pf);
                float gv = tanhfast(pg), ov = sigf(po);
                float cold = c_reg[uc2 * 4 + j];
                float cn = fmaf(fv, cold, iv * gv);
                float hh = ov * tanhfast(cn);
                bool msk = (t < len4[j]);
                c_reg[uc2 * 4 + j] = msk ? cn : cold;
                hnv[j] = msk ? hh : hv[j];
            }
            float4 outv;
            outv.x = hnv[0]; outv.y = hnv[1]; outv.z = hnv[2]; outv.w = hnv[3];
            *(float4*)(hn + u * 64 + w0) = outv;
            __syncthreads();
        }
    }

#pragma unroll
    for (int uc2 = 0; uc2 < 4; uc2++) {
        int u = (uc2 * 2 + sub) * 16 + ug;
        float4 hv = *(const float4*)(hA + u * 64 + w0);
        g_hchar[(wbase + w0 + 0) * HE + u] = hv.x;
        g_hchar[(wbase + w0 + 1) * HE + u] = hv.y;
        g_hchar[(wbase + w0 + 2) * HE + u] = hv.z;
        g_hchar[(wbase + w0 + 3) * HE + u] = hv.w;
    }
}

// ---------------------------------------------------------------------------
// Word-LSTM input gates, char-style k-major GEMM:
//   xg[n][g] = feats[n] @ Wih_p.T + bih_p + bhh_p
// As[k][64 n] from g_featsT; Bs[k][64 g] from g_WpT (both contiguous loads).
// Inner: per k, 1 float4 B + 1 ulonglong2 A + 4 splat + 8 FFMA2 (16 MAC).
// ---------------------------------------------------------------------------
__global__ void __launch_bounds__(256)
xgates_kernel(const float* __restrict__ bih_p,
              const float* __restrict__ bhh_p) {
    __shared__ __align__(16) float As[64 * 64];
    __shared__ __align__(16) float Bs[64 * 64];

    int bg = blockIdx.x;   // 0..15  (gate tile)
    int bn = blockIdx.y;   // 0..127 (word tile)
    int tid = threadIdx.x;

    int n0 = (tid >> 4) << 2;      // word base 0..60
    int g0 = (tid & 15) << 2;      // gate base 0..60 (within tile)

    unsigned long long acc2[2][4];
#pragma unroll
    for (int a = 0; a < 2; a++)
#pragma unroll
        for (int b = 0; b < 4; b++) acc2[a][b] = 0ull;

    for (int kc = 0; kc < 6; kc++) {
        __syncthreads();
        // stage 64x64 tiles; fully contiguous LDG + STS
#pragma unroll
        for (int j = 0; j < 4; j++) {
            int lin = tid + 256 * j;                 // 0..1023 float4 slots
            int k = lin >> 4;
            int c4 = lin & 15;
            *(float4*)(As + k * 64 + c4 * 4) =
                *(const float4*)(g_featsT + (size_t)(kc * 64 + k) * NWORDS
                                 + bn * 64 + c4 * 4);
            *(float4*)(Bs + k * 64 + c4 * 4) =
                *(const float4*)(g_WpT + (size_t)(kc * 64 + k) * G_P
                                 + bg * 64 + c4 * 4);
        }
        __syncthreads();

#pragma unroll 4
        for (int k = 0; k < 64; k++) {
            float4 b = *(const float4*)(Bs + k * 64 + g0);
            ulonglong2 av = *(const ulonglong2*)(As + k * 64 + n0);
            unsigned long long bx, by, bz, bw;
            SPLAT_F32X2(bx, b.x);
            SPLAT_F32X2(by, b.y);
            SPLAT_F32X2(bz, b.z);
            SPLAT_F32X2(bw, b.w);
            FMA_F32X2(acc2[0][0], av.x, bx);
            FMA_F32X2(acc2[0][1], av.x, by);
            FMA_F32X2(acc2[0][2], av.x, bz);
            FMA_F32X2(acc2[0][3], av.x, bw);
            FMA_F32X2(acc2[1][0], av.y, bx);
            FMA_F32X2(acc2[1][1], av.y, by);
            FMA_F32X2(acc2[1][2], av.y, bz);
            FMA_F32X2(acc2[1][3], av.y, bw);
        }
    }

    float accf[4][4];
#pragma unroll
    for (int rp = 0; rp < 2; rp++)
#pragma unroll
        for (int cx = 0; cx < 4; cx++)
            UNPACK_F32X2(accf[2 * rp][cx], accf[2 * rp + 1][cx], acc2[rp][cx]);

    int ggl = bg * 64 + g0;
    float4 bi = *(const float4*)(bih_p + ggl);
    float4 bh = *(const float4*)(bhh_p + ggl);
#pragma unroll
    for (int l = 0; l < 4; l++) {
        float4 o;
        o.x = accf[l][0] + bi.x + bh.x;
        o.y = accf[l][1] + bi.y + bh.y;
        o.z = accf[l][2] + bi.z + bh.z;
        o.w = accf[l][3] + bi.w + bh.w;
        *(float4*)(g_xg + (size_t)(bn * 64 + n0 + l) * G_P + ggl) = o;
    }
}

// ---------------------------------------------------------------------------
// Word LSTM: 16-CTA non-portable cluster, packed f32x2 matvec,
// st.async.b64 broadcast, 4 per-k-slice mbarriers, MUFU activations.
// (round-14 proven; frozen)
// ---------------------------------------------------------------------------
__device__ __forceinline__ uint32_t cluster_rank_() {
    uint32_t r;
    asm("mov.u32 %0, %%cluster_ctarank;" : "=r"(r));
    return r;
}
__device__ __forceinline__ void cluster_sync_() {
    asm volatile("barrier.cluster.arrive.aligned;" ::: "memory");
    asm volatile("barrier.cluster.wait.aligned;" ::: "memory");
}
__device__ __forceinline__ uint32_t mapa_u32(uint32_t la, int r) {
    uint32_t ra;
    asm("mapa.shared::cluster.u32 %0, %1, %2;" : "=r"(ra) : "r"(la), "r"(r));
    return ra;
}
__device__ __forceinline__ void mbar_init_(uint32_t bar, uint32_t cnt) {
    asm volatile("mbarrier.init.shared.b64 [%0], %1;" :: "r"(bar), "r"(cnt) : "memory");
}
__device__ __forceinline__ void mbar_arrive_expect_(uint32_t bar, uint32_t bytes) {
    asm volatile("mbarrier.arrive.expect_tx.shared.b64 _, [%0], %1;"
                 :: "r"(bar), "r"(bytes) : "memory");
}
__device__ __forceinline__ void mbar_wait_parity_(uint32_t bar, uint32_t ph) {
    asm volatile(
        "{\n\t"
        ".reg .pred P1;\n\t"
        "WL_%=:\n\t"
        "mbarrier.try_wait.parity.acquire.cta.shared::cta.b64 P1, [%0], %1, 0x989680;\n\t"
        "@P1 bra.uni WD_%=;\n\t"
        "bra.uni WL_%=;\n\t"
        "WD_%=:\n\t"
        "}"
        :: "r"(bar), "r"(ph) : "memory");
}
__device__ __forceinline__ void st_async_b64_(uint32_t raddr, unsigned long long v,
                                              uint32_t rbar) {
    asm volatile(
        "st.async.shared::cluster.mbarrier::complete_tx::bytes.b64 [%0], %1, [%2];"
        :: "r"(raddr), "l"(v), "r"(rbar) : "memory");
}

__global__ void __launch_bounds__(512, 1) __cluster_dims__(WCLUSTER, 1, 1)
word_lstm_kernel(const float* __restrict__ Whh_p) {
    __shared__ __align__(16) float hbuf[2][HP];      // h double-buffer
    __shared__ __align__(16) float4 pacc4[2][128];
    __shared__ __align__(8) unsigned long long hbar[8];  // [parity*4 + slice64]

    int rank = (int)cluster_rank_();
    int tid = threadIdx.x;
    int w = tid >> 5, lane = tid & 31;
    int q = w & 3;                        // gate quadrant
    int ks2 = w >> 2;                     // 64-wide k-slice 0..3
    int u = lane & 15;                    // unit within CTA
    int khalf = lane >> 4;                // 32-wide half within slice
    int s = ks2 * 2 + khalf;              // 32-wide k-slice 0..7
    int grow = q * HP + rank * 16 + u;    // global gate row 0..1023
    int k0 = ks2 * 64 + khalf * 32;       // this thread's k range [k0, k0+32)

    unsigned long long wreg[16];
    {
        const float* wp = Whh_p + (size_t)grow * HP + k0;
#pragma unroll
        for (int i = 0; i < 8; i++) {
            ulonglong2 v = *(const ulonglong2*)(wp + i * 4);
            wreg[2 * i] = v.x;
            wreg[2 * i + 1] = v.y;
        }
    }

    ((float*)hbuf)[tid] = 0.0f;           // 512 floats = both buffers
    uint32_t bar0 = (uint32_t)__cvta_generic_to_shared(&hbar[0]);
    uint32_t hb0  = (uint32_t)__cvta_generic_to_shared(&hbuf[0][0]);
    if (tid == 0) {
#pragma unroll
        for (int b = 0; b < 8; b++) mbar_init_(bar0 + b * 8, 1);
    }

    uint32_t rd_h[WCLUSTER], rd_b[WCLUSTER];
#pragma unroll
    for (int r = 0; r < WCLUSTER; r++) {
        rd_h[r] = mapa_u32(hb0, r);
        rd_b[r] = mapa_u32(bar0, r);
    }

    bool tail = (w == 15);
    bool xduty = (ks2 == 0 && khalf == 0);
    float c = 0.0f;
    float xc = 0.f, xp = 0.f;
    if (xduty) {
        xc = __ldg(g_xg + grow);
        xp = __ldg(g_xg + (size_t)G_P + grow);
    }
    __syncthreads();
    cluster_sync_();

    uint32_t slice_boff = (uint32_t)((rank >> 2) * 8);

    for (int n = 0; n < NWORDS; n++) {
        int p = n & 1;
        if (n > 0)
            mbar_wait_parity_(bar0 + (uint32_t)((((n - 1) & 1) * 4 + ks2) * 8),
                              (uint32_t)(((n - 1) >> 1) & 1));
        if (tail && lane < 4 && n < NWORDS - 1)
            mbar_arrive_expect_(bar0 + (uint32_t)((p * 4 + lane) * 8), 256u);

        float xn = 0.f;
        if (xduty && n + 2 < NWORDS)
            xn = __ldg(g_xg + (size_t)(n + 2) * G_P + grow);

        const ulonglong2* hp2 = (const ulonglong2*)(&hbuf[p][k0]);
        unsigned long long a0 = 0ull, a1 = 0ull, a2 = 0ull, a3 = 0ull;
#pragma unroll
        for (int i = 0; i < 4; i++) {
            ulonglong2 hvA = hp2[2 * i];
            ulonglong2 hvB = hp2[2 * i + 1];
            FMA_F32X2(a0, wreg[4 * i + 0], hvA.x);
            FMA_F32X2(a1, wreg[4 * i + 1], hvA.y);
            FMA_F32X2(a2, wreg[4 * i + 2], hvB.x);
            FMA_F32X2(a3, wreg[4 * i + 3], hvB.y);
        }
        {
            float l0, h0, l1, h1, l2, h2, l3, h3;
            UNPACK_F32X2(l0, h0, a0);
            UNPACK_F32X2(l1, h1, a1);
            UNPACK_F32X2(l2, h2, a2);
            UNPACK_F32X2(l3, h3, a3);
            float partial = ((l0 + h0) + (l1 + h1)) + ((l2 + h2) + (l3 + h3));
            if (xduty) { partial += xc; xc = xp; xp = xn; }
            ((float*)&pacc4[p][(s >> 2) * 64 + q * 16 + u])[s & 3] = partial;
        }

        if (!tail) {
            asm volatile("bar.arrive 1, 512;" ::: "memory");
        } else {
            asm volatile("bar.sync 1, 512;" ::: "memory");
            float4 ga0 = pacc4[p][u];
            float4 gb0 = pacc4[p][64 + u];
            float4 ga1 = pacc4[p][16 + u];
            float4 gb1 = pacc4[p][80 + u];
            float4 ga2 = pacc4[p][32 + u];
            float4 gb2 = pacc4[p][96 + u];
            float4 ga3 = pacc4[p][48 + u];
            float4 gb3 = pacc4[p][112 + u];
            float s0 = ((ga0.x + ga0.y) + (ga0.z + ga0.w)) +
                       ((gb0.x + gb0.y) + (gb0.z + gb0.w));
            float s1 = ((ga1.x + ga1.y) + (ga1.z + ga1.w)) +
                       ((gb1.x + gb1.y) + (gb1.z + gb1.w));
            float s2 = ((ga2.x + ga2.y) + (ga2.z + ga2.w)) +
                       ((gb2.x + gb2.y) + (gb2.z + gb2.w));
            float s3 = ((ga3.x + ga3.y) + (ga3.z + ga3.w)) +
                       ((gb3.x + gb3.y) + (gb3.z + gb3.w));
            float iv = sig_mufu(s0);
            float fv = sig_mufu(s1);
            float gv = tanh_mufu(s2);
            float ov = sig_mufu(s3);
            c = fmaf(fv, c, iv * gv);
            float hn = ov * tanh_mufu(c);
            if (lane < 16)
                g_hs[(size_t)n * HP + rank * 16 + lane] = hn;

            if (n < NWORDS - 1) {
                float pv = __shfl_xor_sync(0xffffffffu, hn, 1);
                if ((lane & 1) == 0) {
                    unsigned long long hv2;
                    asm("mov.b64 %0, {%1, %2};" : "=l"(hv2) : "f"(hn), "f"(pv));
                    uint32_t off = (uint32_t)((p ^ 1) * (HP * 4) + (rank * 16 + u) * 4);
                    uint32_t boff = (uint32_t)(p * 4 * 8) + slice_boff;
                    int rbase = khalf * 8;
#pragma unroll
                    for (int r = 0; r < 8; r++)
                        st_async_b64_(rd_h[rbase + r] + off, hv2,
                                      rd_b[rbase + r] + boff);
                }
            }
        }
    }
    cluster_sync_();
}

// ---------------------------------------------------------------------------
// Tag projection + log-softmax: one block (64 threads) per word
// ---------------------------------------------------------------------------
__global__ void __launch_bounds__(64)
tag_kernel(const float* __restrict__ W_tag,
           const float* __restrict__ b_tag,
           float* __restrict__ out) {
    __shared__ float hs[HP];
    __shared__ float vals[TAGS];
    __shared__ float red[2];

    int n = blockIdx.x;
    int t = threadIdx.x;
    *(float4*)(hs + t * 4) = *(const float4*)(g_hs + (size_t)n * HP + t * 4);
    __syncthreads();

    if (t < TAGS) {
        const float* wr = W_tag + t * HP;
        float a0 = b_tag[t], a1 = 0.0f, a2 = 0.0f, a3 = 0.0f;
#pragma unroll 8
        for (int k = 0; k < HP; k += 4) {
            float4 wv = *(const float4*)(wr + k);
            a0 = fmaf(wv.x, hs[k + 0], a0);
            a1 = fmaf(wv.y, hs[k + 1], a1);
            a2 = fmaf(wv.z, hs[k + 2], a2);
            a3 = fmaf(wv.w, hs[k + 3], a3);
        }
        vals[t] = (a0 + a1) + (a2 + a3);
    }
    __syncthreads();

    if (t < 32) {
        float m = vals[t];
        if (t + 32 < TAGS) m = fmaxf(m, vals[t + 32]);
#pragma unroll
        for (int o = 16; o > 0; o >>= 1)
            m = fmaxf(m, __shfl_xor_sync(0xffffffffu, m, o));
        float s = expf(vals[t] - m);
        if (t + 32 < TAGS) s += expf(vals[t + 32] - m);
#pragma unroll
        for (int o = 16; o > 0; o >>= 1)
            s += __shfl_xor_sync(0xffffffffu, s, o);
        if (t == 0) { red[0] = m; red[1] = logf(s); }
    }
    __syncthreads();

    if (t < TAGS) out[(size_t)n * TAGS + t] = vals[t] - red[0] - red[1];
}

// ---------------------------------------------------------------------------
// Launch
// ---------------------------------------------------------------------------
extern "C" void kernel_launch(void* const* d_in, const int* in_sizes, int n_in,
                              void* d_out, int out_size) {
    const float* char_emb = (const float*)d_in[0];
    const float* word_emb = (const float*)d_in[1];
    const float* Wih_e    = (const float*)d_in[2];
    const float* Whh_e    = (const float*)d_in[3];
    const float* bih_e    = (const float*)d_in[4];
    const float* bhh_e    = (const float*)d_in[5];
    const float* Wih_p    = (const float*)d_in[6];
    const float* Whh_p    = (const float*)d_in[7];
    const float* bih_p    = (const float*)d_in[8];
    const float* bhh_p    = (const float*)d_in[9];
    const float* W_tag    = (const float*)d_in[10];
    const float* b_tag    = (const float*)d_in[11];
    const int*   sentence = (const int*)d_in[12];
    const int*   char_ids = (const int*)d_in[13];
    const int*   char_len = (const int*)d_in[14];
    float* out = (float*)d_out;

    (void)in_sizes; (void)n_in; (void)out_size;

    cudaFuncSetAttribute(char_lstm_kernel,
                         cudaFuncAttributeMaxDynamicSharedMemorySize,
                         CHAR_SMEM_BYTES);
    cudaFuncSetAttribute(word_lstm_kernel,
                         cudaFuncAttributeNonPortableClusterSizeAllowed, 1);

    prep_table_kernel<<<256, 256>>>(char_emb, Wih_e, bih_e, bhh_e);
    prep_wte_kernel<<<256, 256>>>(Whh_e);
    prep_wpt_kernel<<<1536, 256>>>(Wih_p);

    char_lstm_kernel<<<128, 512, CHAR_SMEM_BYTES>>>(char_ids, char_len);

    feats_transpose_kernel<<<dim3(256, 12), dim3(32, 8)>>>(word_emb, sentence);

    xgates_kernel<<<dim3(16, 128), 256>>>(bih_p, bhh_p);

    word_lstm_kernel<<<WCLUSTER, 512>>>(Whh_p);

    tag_kernel<<<NWORDS, 64>>>(W_tag, b_tag, out);
}